// round 6
// baseline (speedup 1.0000x reference)
#include <cuda_runtime.h>
#include <cstdint>

#define EPS_P 0.001f

// ---------------- scratch (device globals: no allocation, graph-safe) ----------------
__device__ float g_WinT[1024 * 1536];   // in_proj_weight^T  (K=1024 x N=1536)
__device__ float g_WoutT[1024 * 1024];  // out_proj_weight^T (1024 x 1024)
__device__ float g_Q[2048 * 1024];      // projected queries
__device__ float g_K[2048 * 256];       // projected keys
__device__ float g_V[2048 * 256];       // projected values
__device__ float g_KT[256 * 2048];      // keys transposed (embed x token)
__device__ float g_P[32 * 1024 * 1024]; // sigmoid probs -> phi (in place)
__device__ float g_XO[2048 * 1024];     // attention output (token-major, per-head cols)

// ---------------- f32x2 packed-FMA helpers (FFMA2 only reachable via PTX) ----------------
__device__ __forceinline__ unsigned long long fma_f32x2(unsigned long long a,
                                                        unsigned long long b,
                                                        unsigned long long c) {
    unsigned long long d;
    asm("fma.rn.f32x2 %0, %1, %2, %3;" : "=l"(d) : "l"(a), "l"(b), "l"(c));
    return d;
}
__device__ __forceinline__ unsigned long long dup_f32(float x) {
    unsigned long long d;
    asm("mov.b64 %0, {%1, %1};" : "=l"(d) : "f"(x));
    return d;
}
__device__ __forceinline__ float2 unpack_f32x2(unsigned long long v) {
    float2 r;
    asm("mov.b64 {%0, %1}, %2;" : "=f"(r.x), "=f"(r.y) : "l"(v));
    return r;
}

// ---------------- generic NN SGEMM: C(MxN) = A(MxK) * B(KxN) [+bias / sigmoid-clip] ----
// MODE 0: plain (blockIdx.z unused)
// MODE 1: scores   — per-head offsets (A=Q head slice, B=K^T head slice, C=P slice)
// MODE 2: phi @ V  — per-head offsets (A=phi slice, B=V head slice, C=XO head cols)
// EPI  0: none, 1: +bias[n], 2: clamp(sigmoid(x), eps, 1-eps)
template <int BM, int BN, int BK, int TM, int TN, int MODE, int EPI>
__global__ void __launch_bounds__((BM / TM) * (BN / TN))
gemm_nn(const float* __restrict__ A, const float* __restrict__ B, float* __restrict__ C,
        const float* __restrict__ bias, int M, int N, int K,
        int lda, int ldb, int ldc) {
    constexpr int NT = (BM / TM) * (BN / TN);
    constexpr int AVEC = BM * BK / 4;
    constexpr int BVEC = BK * BN / 4;
    constexpr int APT = AVEC / NT;
    constexpr int BPT = BVEC / NT;
    static_assert(AVEC % NT == 0 && BVEC % NT == 0, "tile/thread mismatch");
    static_assert((TM % 2) == 0, "TM even for f32x2");

    __shared__ float As[BK][BM];
    __shared__ float Bs[BK][BN];

    const int z = blockIdx.z;
    if constexpr (MODE == 1) {
        A += (z >> 4) * (1024 * 1024) + (z & 15) * 64;   // Q: batch + q-head col
        B += (z & 3) * (64 * 2048) + (z >> 4) * 1024;    // K^T: kv-head rows + batch cols
        C += z << 20;                                    // P slice
    } else if constexpr (MODE == 2) {
        A += z << 20;                                    // phi slice
        B += (z >> 4) * (1024 * 256) + (z & 3) * 64;     // V: batch rows + kv-head cols
        C += (z >> 4) * (1024 * 1024) + (z & 15) * 64;   // XO: batch + q-head cols
    }

    const int tid = threadIdx.x;
    const int mBlk = blockIdx.y * BM;
    const int nBlk = blockIdx.x * BN;
    const int tn0 = (tid % (BN / TN)) * TN;
    const int tm0 = (tid / (BN / TN)) * TM;
    const int nTiles = K / BK;

    unsigned long long acc[TM / 2][TN];
#pragma unroll
    for (int i = 0; i < TM / 2; i++)
#pragma unroll
        for (int n = 0; n < TN; n++) acc[i][n] = 0ull;

    float4 aReg[APT], bReg[BPT];

    auto loadA = [&](int kt) {
#pragma unroll
        for (int q = 0; q < APT; q++) {
            int v = tid + q * NT;
            int m = v / (BK / 4);
            int kq = v % (BK / 4);
            aReg[q] = *reinterpret_cast<const float4*>(
                A + (size_t)(mBlk + m) * lda + kt * BK + kq * 4);
        }
    };
    auto loadB = [&](int kt) {
#pragma unroll
        for (int q = 0; q < BPT; q++) {
            int v = tid + q * NT;
            int k = v / (BN / 4);
            int nq = v % (BN / 4);
            bReg[q] = *reinterpret_cast<const float4*>(
                B + (size_t)(kt * BK + k) * ldb + nBlk + nq * 4);
        }
    };

    loadA(0);
    loadB(0);

    for (int kt = 0; kt < nTiles; kt++) {
#pragma unroll
        for (int q = 0; q < APT; q++) {
            int v = tid + q * NT;
            int m = v / (BK / 4);
            int kq = v % (BK / 4);
            As[kq * 4 + 0][m] = aReg[q].x;
            As[kq * 4 + 1][m] = aReg[q].y;
            As[kq * 4 + 2][m] = aReg[q].z;
            As[kq * 4 + 3][m] = aReg[q].w;
        }
#pragma unroll
        for (int q = 0; q < BPT; q++) {
            int v = tid + q * NT;
            int k = v / (BN / 4);
            int nq = v % (BN / 4);
            *reinterpret_cast<float4*>(&Bs[k][nq * 4]) = bReg[q];
        }
        __syncthreads();

        if (kt + 1 < nTiles) { loadA(kt + 1); loadB(kt + 1); }

#pragma unroll
        for (int kk = 0; kk < BK; kk++) {
            unsigned long long a2[TM / 2];
            const unsigned long long* ap =
                reinterpret_cast<const unsigned long long*>(&As[kk][tm0]);
#pragma unroll
            for (int i = 0; i < TM / 2; i++) a2[i] = ap[i];

            float bf[TN];
#pragma unroll
            for (int n = 0; n < TN; n += 4) {
                float4 b4 = *reinterpret_cast<const float4*>(&Bs[kk][tn0 + n]);
                bf[n] = b4.x; bf[n + 1] = b4.y; bf[n + 2] = b4.z; bf[n + 3] = b4.w;
            }
#pragma unroll
            for (int n = 0; n < TN; n++) {
                unsigned long long bd = dup_f32(bf[n]);
#pragma unroll
                for (int i = 0; i < TM / 2; i++)
                    acc[i][n] = fma_f32x2(a2[i], bd, acc[i][n]);
            }
        }
        __syncthreads();
    }

    // epilogue
    float bv[TN];
    if constexpr (EPI == 1) {
#pragma unroll
        for (int n = 0; n < TN; n++) bv[n] = bias[nBlk + tn0 + n];
    }
#pragma unroll
    for (int i = 0; i < TM / 2; i++) {
        float r0[TN], r1[TN];
#pragma unroll
        for (int n = 0; n < TN; n++) {
            float2 u = unpack_f32x2(acc[i][n]);
            r0[n] = u.x;
            r1[n] = u.y;
        }
#pragma unroll
        for (int n = 0; n < TN; n++) {
            if constexpr (EPI == 1) {
                r0[n] += bv[n];
                r1[n] += bv[n];
            } else if constexpr (EPI == 2) {
                r0[n] = fminf(fmaxf(1.f / (1.f + __expf(-r0[n])), EPS_P), 1.f - EPS_P);
                r1[n] = fminf(fmaxf(1.f / (1.f + __expf(-r1[n])), EPS_P), 1.f - EPS_P);
            }
        }
        size_t row0 = (size_t)(mBlk + tm0 + 2 * i) * ldc + nBlk + tn0;
#pragma unroll
        for (int n = 0; n < TN; n += 4) {
            *reinterpret_cast<float4*>(C + row0 + n) =
                make_float4(r0[n], r0[n + 1], r0[n + 2], r0[n + 3]);
            *reinterpret_cast<float4*>(C + row0 + ldc + n) =
                make_float4(r1[n], r1[n + 1], r1[n + 2], r1[n + 3]);
        }
    }
}

// ---------------- transpose: out(C x R) = in(R x C)^T ----------------
__global__ void transpose_kernel(const float* __restrict__ in, float* __restrict__ out,
                                 int R, int C) {
    __shared__ float tile[32][33];
    int c0 = blockIdx.x * 32;
    int r0 = blockIdx.y * 32;
    int x = threadIdx.x, y0 = threadIdx.y;
#pragma unroll
    for (int yy = y0; yy < 32; yy += 8) {
        int r = r0 + yy, c = c0 + x;
        if (r < R && c < C) tile[yy][x] = in[(size_t)r * C + c];
    }
    __syncthreads();
#pragma unroll
    for (int yy = y0; yy < 32; yy += 8) {
        int c = c0 + yy, r = r0 + x;
        if (r < R && c < C) out[(size_t)c * R + r] = tile[x][yy];
    }
}

// ---------------- monotonic attention scan (in place over P) ----------------
// phi[i,j] = (1 - p[i,j-1]) * phi[i,j-1] + p[i-1,j] * phi[i-1,j]; phi[0] = onehot(0).
// One block per (batch, head). 128 threads x 8 elements. Row recurrence solved by
// per-thread affine compose + warp shfl scan + 4-warp smem prefix (parity buffered).
__global__ void __launch_bounds__(128) monotonic_scan_kernel(float* __restrict__ P) {
    float* p = P + ((size_t)blockIdx.x << 20);
    const int tid = threadIdx.x;
    const int lane = tid & 31;
    const int wid = tid >> 5;
    const int j0 = tid << 3;
    __shared__ float aggA[2][4], aggB[2][4];

    float pPrev[8], phiPrev[8], cur[8];

    {
        float4 t0 = *reinterpret_cast<const float4*>(p + j0);
        float4 t1 = *reinterpret_cast<const float4*>(p + j0 + 4);
        pPrev[0] = t0.x; pPrev[1] = t0.y; pPrev[2] = t0.z; pPrev[3] = t0.w;
        pPrev[4] = t1.x; pPrev[5] = t1.y; pPrev[6] = t1.z; pPrev[7] = t1.w;
    }
#pragma unroll
    for (int x = 0; x < 8; x++) phiPrev[x] = 0.f;
    if (tid == 0) phiPrev[0] = 1.f;
    // write phi row 0 (p row 0 already consumed into registers)
    *reinterpret_cast<float4*>(p + j0) =
        make_float4(phiPrev[0], phiPrev[1], phiPrev[2], phiPrev[3]);
    *reinterpret_cast<float4*>(p + j0 + 4) =
        make_float4(phiPrev[4], phiPrev[5], phiPrev[6], phiPrev[7]);

    float curLeft;
    {
        const float* r = p + 1024;
        float4 c0 = *reinterpret_cast<const float4*>(r + j0);
        float4 c1 = *reinterpret_cast<const float4*>(r + j0 + 4);
        cur[0] = c0.x; cur[1] = c0.y; cur[2] = c0.z; cur[3] = c0.w;
        cur[4] = c1.x; cur[5] = c1.y; cur[6] = c1.z; cur[7] = c1.w;
        curLeft = (tid == 0) ? 0.f : r[j0 - 1];
    }

    for (int i = 1; i < 1024; i++) {
        // prefetch next row (hides DRAM latency behind this row's scan)
        float nxt[8];
        float nxtLeft = 0.f;
        if (i + 1 < 1024) {
            const float* r = p + (size_t)(i + 1) * 1024;
            float4 c0 = *reinterpret_cast<const float4*>(r + j0);
            float4 c1 = *reinterpret_cast<const float4*>(r + j0 + 4);
            nxt[0] = c0.x; nxt[1] = c0.y; nxt[2] = c0.z; nxt[3] = c0.w;
            nxt[4] = c1.x; nxt[5] = c1.y; nxt[6] = c1.z; nxt[7] = c1.w;
            nxtLeft = (tid == 0) ? 0.f : r[j0 - 1];
        }

        float A[8], a[8];
        A[0] = (tid == 0) ? 0.f : (1.f - curLeft);
#pragma unroll
        for (int x = 1; x < 8; x++) A[x] = 1.f - cur[x - 1];
#pragma unroll
        for (int x = 0; x < 8; x++) a[x] = phiPrev[x] * pPrev[x];

        // per-thread affine compose over 8 elements
        float Ac = A[0], bc = a[0];
#pragma unroll
        for (int x = 1; x < 8; x++) {
            bc = fmaf(bc, A[x], a[x]);
            Ac *= A[x];
        }

        // warp inclusive scan of (A,b)
        float sA = Ac, sB = bc;
#pragma unroll
        for (int d = 1; d < 32; d <<= 1) {
            float oA = __shfl_up_sync(0xffffffffu, sA, d);
            float oB = __shfl_up_sync(0xffffffffu, sB, d);
            if (lane >= d) {
                sB = fmaf(oB, sA, sB);
                sA = oA * sA;
            }
        }

        const int par = i & 1;
        if (lane == 31) {
            aggA[par][wid] = sA;
            aggB[par][wid] = sB;
        }
        __syncthreads();

        // prefix over preceding warps (y before this warp's first element)
        float yw = 0.f;
#pragma unroll
        for (int w = 0; w < 3; w++)
            if (w < wid) yw = fmaf(yw, aggA[par][w], aggB[par][w]);

        // exclusive within warp
        float eA = __shfl_up_sync(0xffffffffu, sA, 1);
        float eB = __shfl_up_sync(0xffffffffu, sB, 1);
        if (lane == 0) { eA = 1.f; eB = 0.f; }
        float y = fmaf(yw, eA, eB);  // phi value just before this thread's chunk

        // serial fixup -> phi row i values
#pragma unroll
        for (int x = 0; x < 8; x++) {
            y = fmaf(A[x], y, a[x]);
            phiPrev[x] = y;
        }

        float* orow = p + (size_t)i * 1024 + j0;
        *reinterpret_cast<float4*>(orow) =
            make_float4(phiPrev[0], phiPrev[1], phiPrev[2], phiPrev[3]);
        *reinterpret_cast<float4*>(orow + 4) =
            make_float4(phiPrev[4], phiPrev[5], phiPrev[6], phiPrev[7]);

#pragma unroll
        for (int x = 0; x < 8; x++) pPrev[x] = cur[x];
        if (i + 1 < 1024) {
#pragma unroll
            for (int x = 0; x < 8; x++) cur[x] = nxt[x];
            curLeft = nxtLeft;
        }
    }
}

// ---------------- launch ----------------
extern "C" void kernel_launch(void* const* d_in, const int* in_sizes, int n_in,
                              void* d_out, int out_size) {
    (void)in_sizes; (void)n_in; (void)out_size;
    const float* query = (const float*)d_in[0];
    const float* key   = (const float*)d_in[1];
    const float* value = (const float*)d_in[2];
    const float* Win   = (const float*)d_in[3];
    const float* bin   = (const float*)d_in[4];
    const float* Wout  = (const float*)d_in[5];
    const float* bout  = (const float*)d_in[6];
    float* out = (float*)d_out;

    float *WinT, *WoutT, *Q, *Kb, *Vb, *KT, *P, *XO;
    cudaGetSymbolAddress((void**)&WinT, g_WinT);
    cudaGetSymbolAddress((void**)&WoutT, g_WoutT);
    cudaGetSymbolAddress((void**)&Q, g_Q);
    cudaGetSymbolAddress((void**)&Kb, g_K);
    cudaGetSymbolAddress((void**)&Vb, g_V);
    cudaGetSymbolAddress((void**)&KT, g_KT);
    cudaGetSymbolAddress((void**)&P, g_P);
    cudaGetSymbolAddress((void**)&XO, g_XO);

    dim3 tb(32, 8);
    // weight transposes (W is (out,in); we need (in,out) for NN GEMM)
    transpose_kernel<<<dim3(1024 / 32, 1536 / 32), tb>>>(Win, WinT, 1536, 1024);
    transpose_kernel<<<dim3(1024 / 32, 1024 / 32), tb>>>(Wout, WoutT, 1024, 1024);

    // Q projection: (2048x1024) = query (2048x1024) @ WinT[:, 0:1024]
    gemm_nn<128, 128, 16, 8, 8, 0, 1><<<dim3(8, 16, 1), 256>>>(
        query, WinT, Q, bin, 2048, 1024, 1024, 1024, 1536, 1024);
    // K projection: (2048x256) = key @ WinT[:, 1024:1280]
    gemm_nn<64, 128, 16, 8, 8, 0, 1><<<dim3(2, 32, 1), 128>>>(
        key, WinT + 1024, Kb, bin + 1024, 2048, 256, 1024, 1024, 1536, 256);
    // V projection: (2048x256) = value @ WinT[:, 1280:1536]
    gemm_nn<64, 128, 16, 8, 8, 0, 1><<<dim3(2, 32, 1), 128>>>(
        value, WinT + 1280, Vb, bin + 1280, 2048, 256, 1024, 1024, 1536, 256);

    // K transpose to (embed x token) for NN score GEMM
    transpose_kernel<<<dim3(256 / 32, 2048 / 32), tb>>>(Kb, KT, 2048, 256);

    // scores per head: P = clamp(sigmoid(Qh @ Kh^T), eps, 1-eps); 32 heads in grid.z
    gemm_nn<128, 128, 16, 8, 8, 1, 2><<<dim3(8, 8, 32), 256>>>(
        Q, KT, P, nullptr, 1024, 1024, 64, 1024, 2048, 1024);

    // monotonic attention recurrence (in place: P -> phi)
    monotonic_scan_kernel<<<32, 128>>>(P);

    // O = phi @ V per head, scattered into XO (token-major, per-head columns)
    gemm_nn<128, 64, 16, 8, 8, 2, 0><<<dim3(1, 8, 32), 128>>>(
        P, Vb, XO, nullptr, 1024, 64, 1024, 1024, 256, 1024);

    // output projection
    gemm_nn<128, 128, 16, 8, 8, 0, 1><<<dim3(8, 16, 1), 256>>>(
        XO, WoutT, out, bout, 2048, 1024, 1024, 1024, 1024, 1024);
}

// round 7
// speedup vs baseline: 1.0111x; 1.0111x over previous
#include <cuda_runtime.h>
#include <cstdint>

#define EPS_P 0.001f

// ---------------- scratch (device globals: no allocation, graph-safe) ----------------
__device__ float g_WinT[1024 * 1536];   // in_proj_weight^T  (K=1024 x N=1536)
__device__ float g_WoutT[1024 * 1024];  // out_proj_weight^T (1024 x 1024)
__device__ float g_Q[2048 * 1024];      // projected queries
__device__ float g_K[2048 * 256];       // projected keys
__device__ float g_V[2048 * 256];       // projected values
__device__ float g_KT[256 * 2048];      // keys transposed (embed x token)
__device__ float g_P[32 * 1024 * 1024]; // sigmoid probs -> phi (in place)
__device__ float g_XO[2048 * 1024];     // attention output (token-major, per-head cols)

// ---------------- f32x2 packed-FMA helpers (FFMA2 only reachable via PTX) ----------------
__device__ __forceinline__ unsigned long long fma_f32x2(unsigned long long a,
                                                        unsigned long long b,
                                                        unsigned long long c) {
    unsigned long long d;
    asm("fma.rn.f32x2 %0, %1, %2, %3;" : "=l"(d) : "l"(a), "l"(b), "l"(c));
    return d;
}
__device__ __forceinline__ unsigned long long dup_f32(float x) {
    unsigned long long d;
    asm("mov.b64 %0, {%1, %1};" : "=l"(d) : "f"(x));
    return d;
}
__device__ __forceinline__ float2 unpack_f32x2(unsigned long long v) {
    float2 r;
    asm("mov.b64 {%0, %1}, %2;" : "=f"(r.x), "=f"(r.y) : "l"(v));
    return r;
}

// ---------------- generic NN SGEMM: C(MxN) = A(MxK) * B(KxN) [+bias / sigmoid-clip] ----
// MODE 0: plain (blockIdx.z unused)
// MODE 1: scores   — per-head offsets (A=Q head slice, B=K^T head slice, C=P slice)
// MODE 2: phi @ V  — per-head offsets (A=phi slice, B=V head slice, C=XO head cols)
// EPI  0: none, 1: +bias[n], 2: clamp(sigmoid(x), eps, 1-eps)
template <int BM, int BN, int BK, int TM, int TN, int MODE, int EPI>
__global__ void __launch_bounds__((BM / TM) * (BN / TN))
gemm_nn(const float* __restrict__ A, const float* __restrict__ B, float* __restrict__ C,
        const float* __restrict__ bias, int M, int N, int K,
        int lda, int ldb, int ldc) {
    constexpr int NT = (BM / TM) * (BN / TN);
    constexpr int AVEC = BM * BK / 4;
    constexpr int BVEC = BK * BN / 4;
    constexpr int APT = AVEC / NT;
    constexpr int BPT = BVEC / NT;
    static_assert(AVEC % NT == 0 && BVEC % NT == 0, "tile/thread mismatch");
    static_assert((TM % 2) == 0, "TM even for f32x2");

    __shared__ float As[BK][BM];
    __shared__ float Bs[BK][BN];

    const int z = blockIdx.z;
    if constexpr (MODE == 1) {
        A += (z >> 4) * (1024 * 1024) + (z & 15) * 64;   // Q: batch + q-head col
        B += (z & 3) * (64 * 2048) + (z >> 4) * 1024;    // K^T: kv-head rows + batch cols
        C += z << 20;                                    // P slice
    } else if constexpr (MODE == 2) {
        A += z << 20;                                    // phi slice
        B += (z >> 4) * (1024 * 256) + (z & 3) * 64;     // V: batch rows + kv-head cols
        C += (z >> 4) * (1024 * 1024) + (z & 15) * 64;   // XO: batch + q-head cols
    }

    const int tid = threadIdx.x;
    const int mBlk = blockIdx.y * BM;
    const int nBlk = blockIdx.x * BN;
    const int tn0 = (tid % (BN / TN)) * TN;
    const int tm0 = (tid / (BN / TN)) * TM;
    const int nTiles = K / BK;

    unsigned long long acc[TM / 2][TN];
#pragma unroll
    for (int i = 0; i < TM / 2; i++)
#pragma unroll
        for (int n = 0; n < TN; n++) acc[i][n] = 0ull;

    float4 aReg[APT], bReg[BPT];

    auto loadA = [&](int kt) {
#pragma unroll
        for (int q = 0; q < APT; q++) {
            int v = tid + q * NT;
            int m = v / (BK / 4);
            int kq = v % (BK / 4);
            aReg[q] = *reinterpret_cast<const float4*>(
                A + (size_t)(mBlk + m) * lda + kt * BK + kq * 4);
        }
    };
    auto loadB = [&](int kt) {
#pragma unroll
        for (int q = 0; q < BPT; q++) {
            int v = tid + q * NT;
            int k = v / (BN / 4);
            int nq = v % (BN / 4);
            bReg[q] = *reinterpret_cast<const float4*>(
                B + (size_t)(kt * BK + k) * ldb + nBlk + nq * 4);
        }
    };

    loadA(0);
    loadB(0);

    for (int kt = 0; kt < nTiles; kt++) {
#pragma unroll
        for (int q = 0; q < APT; q++) {
            int v = tid + q * NT;
            int m = v / (BK / 4);
            int kq = v % (BK / 4);
            As[kq * 4 + 0][m] = aReg[q].x;
            As[kq * 4 + 1][m] = aReg[q].y;
            As[kq * 4 + 2][m] = aReg[q].z;
            As[kq * 4 + 3][m] = aReg[q].w;
        }
#pragma unroll
        for (int q = 0; q < BPT; q++) {
            int v = tid + q * NT;
            int k = v / (BN / 4);
            int nq = v % (BN / 4);
            *reinterpret_cast<float4*>(&Bs[k][nq * 4]) = bReg[q];
        }
        __syncthreads();

        if (kt + 1 < nTiles) { loadA(kt + 1); loadB(kt + 1); }

#pragma unroll
        for (int kk = 0; kk < BK; kk++) {
            unsigned long long a2[TM / 2];
            const unsigned long long* ap =
                reinterpret_cast<const unsigned long long*>(&As[kk][tm0]);
#pragma unroll
            for (int i = 0; i < TM / 2; i++) a2[i] = ap[i];

            float bf[TN];
#pragma unroll
            for (int n = 0; n < TN; n += 4) {
                float4 b4 = *reinterpret_cast<const float4*>(&Bs[kk][tn0 + n]);
                bf[n] = b4.x; bf[n + 1] = b4.y; bf[n + 2] = b4.z; bf[n + 3] = b4.w;
            }
#pragma unroll
            for (int n = 0; n < TN; n++) {
                unsigned long long bd = dup_f32(bf[n]);
#pragma unroll
                for (int i = 0; i < TM / 2; i++)
                    acc[i][n] = fma_f32x2(a2[i], bd, acc[i][n]);
            }
        }
        __syncthreads();
    }

    // epilogue
    float bv[TN];
    if constexpr (EPI == 1) {
#pragma unroll
        for (int n = 0; n < TN; n++) bv[n] = bias[nBlk + tn0 + n];
    }
#pragma unroll
    for (int i = 0; i < TM / 2; i++) {
        float r0[TN], r1[TN];
#pragma unroll
        for (int n = 0; n < TN; n++) {
            float2 u = unpack_f32x2(acc[i][n]);
            r0[n] = u.x;
            r1[n] = u.y;
        }
#pragma unroll
        for (int n = 0; n < TN; n++) {
            if constexpr (EPI == 1) {
                r0[n] += bv[n];
                r1[n] += bv[n];
            } else if constexpr (EPI == 2) {
                r0[n] = fminf(fmaxf(1.f / (1.f + __expf(-r0[n])), EPS_P), 1.f - EPS_P);
                r1[n] = fminf(fmaxf(1.f / (1.f + __expf(-r1[n])), EPS_P), 1.f - EPS_P);
            }
        }
        size_t row0 = (size_t)(mBlk + tm0 + 2 * i) * ldc + nBlk + tn0;
#pragma unroll
        for (int n = 0; n < TN; n += 4) {
            *reinterpret_cast<float4*>(C + row0 + n) =
                make_float4(r0[n], r0[n + 1], r0[n + 2], r0[n + 3]);
            *reinterpret_cast<float4*>(C + row0 + ldc + n) =
                make_float4(r1[n], r1[n + 1], r1[n + 2], r1[n + 3]);
        }
    }
}

// ---------------- transpose: out(C x R) = in(R x C)^T ----------------
__global__ void transpose_kernel(const float* __restrict__ in, float* __restrict__ out,
                                 int R, int C) {
    __shared__ float tile[32][33];
    int c0 = blockIdx.x * 32;
    int r0 = blockIdx.y * 32;
    int x = threadIdx.x, y0 = threadIdx.y;
#pragma unroll
    for (int yy = y0; yy < 32; yy += 8) {
        int r = r0 + yy, c = c0 + x;
        if (r < R && c < C) tile[yy][x] = in[(size_t)r * C + c];
    }
    __syncthreads();
#pragma unroll
    for (int yy = y0; yy < 32; yy += 8) {
        int c = c0 + yy, r = r0 + x;
        if (r < R && c < C) out[(size_t)c * R + r] = tile[x][yy];
    }
}

// ---------------- monotonic attention scan (in place over P) ----------------
// phi[i,j] = (1 - p[i,j-1]) * phi[i,j-1] + p[i-1,j] * phi[i-1,j]; phi[0] = onehot(0).
// One block per (batch, head). 128 threads x 8 elements. Row recurrence solved by
// per-thread affine compose + warp shfl scan + 4-warp smem prefix (parity buffered).
__global__ void __launch_bounds__(128) monotonic_scan_kernel(float* __restrict__ P) {
    float* p = P + ((size_t)blockIdx.x << 20);
    const int tid = threadIdx.x;
    const int lane = tid & 31;
    const int wid = tid >> 5;
    const int j0 = tid << 3;
    __shared__ float aggA[2][4], aggB[2][4];

    float pPrev[8], phiPrev[8], cur[8];

    {
        float4 t0 = *reinterpret_cast<const float4*>(p + j0);
        float4 t1 = *reinterpret_cast<const float4*>(p + j0 + 4);
        pPrev[0] = t0.x; pPrev[1] = t0.y; pPrev[2] = t0.z; pPrev[3] = t0.w;
        pPrev[4] = t1.x; pPrev[5] = t1.y; pPrev[6] = t1.z; pPrev[7] = t1.w;
    }
#pragma unroll
    for (int x = 0; x < 8; x++) phiPrev[x] = 0.f;
    if (tid == 0) phiPrev[0] = 1.f;
    // write phi row 0 (p row 0 already consumed into registers)
    *reinterpret_cast<float4*>(p + j0) =
        make_float4(phiPrev[0], phiPrev[1], phiPrev[2], phiPrev[3]);
    *reinterpret_cast<float4*>(p + j0 + 4) =
        make_float4(phiPrev[4], phiPrev[5], phiPrev[6], phiPrev[7]);

    float curLeft;
    {
        const float* r = p + 1024;
        float4 c0 = *reinterpret_cast<const float4*>(r + j0);
        float4 c1 = *reinterpret_cast<const float4*>(r + j0 + 4);
        cur[0] = c0.x; cur[1] = c0.y; cur[2] = c0.z; cur[3] = c0.w;
        cur[4] = c1.x; cur[5] = c1.y; cur[6] = c1.z; cur[7] = c1.w;
        curLeft = (tid == 0) ? 0.f : r[j0 - 1];
    }

    for (int i = 1; i < 1024; i++) {
        // prefetch next row (hides DRAM latency behind this row's scan)
        float nxt[8];
        float nxtLeft = 0.f;
        if (i + 1 < 1024) {
            const float* r = p + (size_t)(i + 1) * 1024;
            float4 c0 = *reinterpret_cast<const float4*>(r + j0);
            float4 c1 = *reinterpret_cast<const float4*>(r + j0 + 4);
            nxt[0] = c0.x; nxt[1] = c0.y; nxt[2] = c0.z; nxt[3] = c0.w;
            nxt[4] = c1.x; nxt[5] = c1.y; nxt[6] = c1.z; nxt[7] = c1.w;
            nxtLeft = (tid == 0) ? 0.f : r[j0 - 1];
        }

        float A[8], a[8];
        A[0] = (tid == 0) ? 0.f : (1.f - curLeft);
#pragma unroll
        for (int x = 1; x < 8; x++) A[x] = 1.f - cur[x - 1];
#pragma unroll
        for (int x = 0; x < 8; x++) a[x] = phiPrev[x] * pPrev[x];

        // per-thread affine compose over 8 elements
        float Ac = A[0], bc = a[0];
#pragma unroll
        for (int x = 1; x < 8; x++) {
            bc = fmaf(bc, A[x], a[x]);
            Ac *= A[x];
        }

        // warp inclusive scan of (A,b)
        float sA = Ac, sB = bc;
#pragma unroll
        for (int d = 1; d < 32; d <<= 1) {
            float oA = __shfl_up_sync(0xffffffffu, sA, d);
            float oB = __shfl_up_sync(0xffffffffu, sB, d);
            if (lane >= d) {
                sB = fmaf(oB, sA, sB);
                sA = oA * sA;
            }
        }

        const int par = i & 1;
        if (lane == 31) {
            aggA[par][wid] = sA;
            aggB[par][wid] = sB;
        }
        __syncthreads();

        // prefix over preceding warps (y before this warp's first element)
        float yw = 0.f;
#pragma unroll
        for (int w = 0; w < 3; w++)
            if (w < wid) yw = fmaf(yw, aggA[par][w], aggB[par][w]);

        // exclusive within warp
        float eA = __shfl_up_sync(0xffffffffu, sA, 1);
        float eB = __shfl_up_sync(0xffffffffu, sB, 1);
        if (lane == 0) { eA = 1.f; eB = 0.f; }
        float y = fmaf(yw, eA, eB);  // phi value just before this thread's chunk

        // serial fixup -> phi row i values
#pragma unroll
        for (int x = 0; x < 8; x++) {
            y = fmaf(A[x], y, a[x]);
            phiPrev[x] = y;
        }

        float* orow = p + (size_t)i * 1024 + j0;
        *reinterpret_cast<float4*>(orow) =
            make_float4(phiPrev[0], phiPrev[1], phiPrev[2], phiPrev[3]);
        *reinterpret_cast<float4*>(orow + 4) =
            make_float4(phiPrev[4], phiPrev[5], phiPrev[6], phiPrev[7]);

#pragma unroll
        for (int x = 0; x < 8; x++) pPrev[x] = cur[x];
        if (i + 1 < 1024) {
#pragma unroll
            for (int x = 0; x < 8; x++) cur[x] = nxt[x];
            curLeft = nxtLeft;
        }
    }
}

// ---------------- launch ----------------
extern "C" void kernel_launch(void* const* d_in, const int* in_sizes, int n_in,
                              void* d_out, int out_size) {
    (void)in_sizes; (void)n_in; (void)out_size;
    const float* query = (const float*)d_in[0];
    const float* key   = (const float*)d_in[1];
    const float* value = (const float*)d_in[2];
    const float* Win   = (const float*)d_in[3];
    const float* bin   = (const float*)d_in[4];
    const float* Wout  = (const float*)d_in[5];
    const float* bout  = (const float*)d_in[6];
    float* out = (float*)d_out;

    float *WinT, *WoutT, *Q, *Kb, *Vb, *KT, *P, *XO;
    cudaGetSymbolAddress((void**)&WinT, g_WinT);
    cudaGetSymbolAddress((void**)&WoutT, g_WoutT);
    cudaGetSymbolAddress((void**)&Q, g_Q);
    cudaGetSymbolAddress((void**)&Kb, g_K);
    cudaGetSymbolAddress((void**)&Vb, g_V);
    cudaGetSymbolAddress((void**)&KT, g_KT);
    cudaGetSymbolAddress((void**)&P, g_P);
    cudaGetSymbolAddress((void**)&XO, g_XO);

    dim3 tb(32, 8);
    // weight transposes (W is (out,in); we need (in,out) for NN GEMM)
    transpose_kernel<<<dim3(1024 / 32, 1536 / 32), tb>>>(Win, WinT, 1536, 1024);
    transpose_kernel<<<dim3(1024 / 32, 1024 / 32), tb>>>(Wout, WoutT, 1024, 1024);

    // Q projection: (2048x1024) = query (2048x1024) @ WinT[:, 0:1024]
    gemm_nn<128, 128, 16, 8, 8, 0, 1><<<dim3(8, 16, 1), 256>>>(
        query, WinT, Q, bin, 2048, 1024, 1024, 1024, 1536, 1024);
    // K projection: (2048x256) = key @ WinT[:, 1024:1280]
    gemm_nn<64, 128, 16, 8, 8, 0, 1><<<dim3(2, 32, 1), 128>>>(
        key, WinT + 1024, Kb, bin + 1024, 2048, 256, 1024, 1024, 1536, 256);
    // V projection: (2048x256) = value @ WinT[:, 1280:1536]
    gemm_nn<64, 128, 16, 8, 8, 0, 1><<<dim3(2, 32, 1), 128>>>(
        value, WinT + 1280, Vb, bin + 1280, 2048, 256, 1024, 1024, 1536, 256);

    // K transpose to (embed x token) for NN score GEMM
    transpose_kernel<<<dim3(256 / 32, 2048 / 32), tb>>>(Kb, KT, 2048, 256);

    // scores per head: P = clamp(sigmoid(Qh @ Kh^T), eps, 1-eps); 32 heads in grid.z
    gemm_nn<128, 128, 16, 8, 8, 1, 2><<<dim3(8, 8, 32), 256>>>(
        Q, KT, P, nullptr, 1024, 1024, 64, 1024, 2048, 1024);

    // monotonic attention recurrence (in place: P -> phi)
    monotonic_scan_kernel<<<32, 128>>>(P);

    // O = phi @ V per head, scattered into XO (token-major, per-head columns)
    gemm_nn<128, 64, 16, 8, 8, 2, 0><<<dim3(1, 8, 32), 128>>>(
        P, Vb, XO, nullptr, 1024, 64, 1024, 1024, 256, 1024);

    // output projection
    gemm_nn<128, 128, 16, 8, 8, 0, 1><<<dim3(8, 16, 1), 256>>>(
        XO, WoutT, out, bout, 2048, 1024, 1024, 1024, 1024, 1024);
}

// round 8
// speedup vs baseline: 1.0124x; 1.0013x over previous
#include <cuda_runtime.h>
#include <cstdint>

#define EPS_P 0.001f

// ---------------- scratch (device globals: no allocation, graph-safe) ----------------
__device__ float g_WinT[1024 * 1536];   // in_proj_weight^T  (K=1024 x N=1536)
__device__ float g_WoutT[1024 * 1024];  // out_proj_weight^T (1024 x 1024)
__device__ float g_Q[2048 * 1024];      // projected queries
__device__ float g_K[2048 * 256];       // projected keys
__device__ float g_V[2048 * 256];       // projected values
__device__ float g_KT[256 * 2048];      // keys transposed (embed x token)
__device__ float g_P[32 * 1024 * 1024]; // sigmoid probs -> phi (in place)
__device__ float g_XO[2048 * 1024];     // attention output (token-major, per-head cols)

// ---------------- f32x2 packed-FMA helpers (FFMA2 only reachable via PTX) ----------------
__device__ __forceinline__ unsigned long long fma_f32x2(unsigned long long a,
                                                        unsigned long long b,
                                                        unsigned long long c) {
    unsigned long long d;
    asm("fma.rn.f32x2 %0, %1, %2, %3;" : "=l"(d) : "l"(a), "l"(b), "l"(c));
    return d;
}
__device__ __forceinline__ unsigned long long dup_f32(float x) {
    unsigned long long d;
    asm("mov.b64 %0, {%1, %1};" : "=l"(d) : "f"(x));
    return d;
}
__device__ __forceinline__ float2 unpack_f32x2(unsigned long long v) {
    float2 r;
    asm("mov.b64 {%0, %1}, %2;" : "=f"(r.x), "=f"(r.y) : "l"(v));
    return r;
}

// ---------------- generic NN SGEMM: C(MxN) = A(MxK) * B(KxN) [+bias / sigmoid-clip] ----
// MODE 0: plain (blockIdx.z unused)
// MODE 1: scores   — per-head offsets (A=Q head slice, B=K^T head slice, C=P slice)
// MODE 2: phi @ V  — per-head offsets (A=phi slice, B=V head slice, C=XO head cols)
// EPI  0: none, 1: +bias[n], 2: clamp(sigmoid(x), eps, 1-eps)
template <int BM, int BN, int BK, int TM, int TN, int MODE, int EPI>
__global__ void __launch_bounds__((BM / TM) * (BN / TN))
gemm_nn(const float* __restrict__ A, const float* __restrict__ B, float* __restrict__ C,
        const float* __restrict__ bias, int M, int N, int K,
        int lda, int ldb, int ldc) {
    constexpr int NT = (BM / TM) * (BN / TN);
    constexpr int AVEC = BM * BK / 4;
    constexpr int BVEC = BK * BN / 4;
    constexpr int APT = AVEC / NT;
    constexpr int BPT = BVEC / NT;
    static_assert(AVEC % NT == 0 && BVEC % NT == 0, "tile/thread mismatch");
    static_assert((TM % 2) == 0, "TM even for f32x2");

    __shared__ float As[BK][BM];
    __shared__ float Bs[BK][BN];

    const int z = blockIdx.z;
    if constexpr (MODE == 1) {
        A += (z >> 4) * (1024 * 1024) + (z & 15) * 64;   // Q: batch + q-head col
        B += (z & 3) * (64 * 2048) + (z >> 4) * 1024;    // K^T: kv-head rows + batch cols
        C += z << 20;                                    // P slice
    } else if constexpr (MODE == 2) {
        A += z << 20;                                    // phi slice
        B += (z >> 4) * (1024 * 256) + (z & 3) * 64;     // V: batch rows + kv-head cols
        C += (z >> 4) * (1024 * 1024) + (z & 15) * 64;   // XO: batch + q-head cols
    }

    const int tid = threadIdx.x;
    const int mBlk = blockIdx.y * BM;
    const int nBlk = blockIdx.x * BN;
    const int tn0 = (tid % (BN / TN)) * TN;
    const int tm0 = (tid / (BN / TN)) * TM;
    const int nTiles = K / BK;

    unsigned long long acc[TM / 2][TN];
#pragma unroll
    for (int i = 0; i < TM / 2; i++)
#pragma unroll
        for (int n = 0; n < TN; n++) acc[i][n] = 0ull;

    float4 aReg[APT], bReg[BPT];

    auto loadA = [&](int kt) {
#pragma unroll
        for (int q = 0; q < APT; q++) {
            int v = tid + q * NT;
            int m = v / (BK / 4);
            int kq = v % (BK / 4);
            aReg[q] = *reinterpret_cast<const float4*>(
                A + (size_t)(mBlk + m) * lda + kt * BK + kq * 4);
        }
    };
    auto loadB = [&](int kt) {
#pragma unroll
        for (int q = 0; q < BPT; q++) {
            int v = tid + q * NT;
            int k = v / (BN / 4);
            int nq = v % (BN / 4);
            bReg[q] = *reinterpret_cast<const float4*>(
                B + (size_t)(kt * BK + k) * ldb + nBlk + nq * 4);
        }
    };

    loadA(0);
    loadB(0);

    for (int kt = 0; kt < nTiles; kt++) {
#pragma unroll
        for (int q = 0; q < APT; q++) {
            int v = tid + q * NT;
            int m = v / (BK / 4);
            int kq = v % (BK / 4);
            As[kq * 4 + 0][m] = aReg[q].x;
            As[kq * 4 + 1][m] = aReg[q].y;
            As[kq * 4 + 2][m] = aReg[q].z;
            As[kq * 4 + 3][m] = aReg[q].w;
        }
#pragma unroll
        for (int q = 0; q < BPT; q++) {
            int v = tid + q * NT;
            int k = v / (BN / 4);
            int nq = v % (BN / 4);
            *reinterpret_cast<float4*>(&Bs[k][nq * 4]) = bReg[q];
        }
        __syncthreads();

        if (kt + 1 < nTiles) { loadA(kt + 1); loadB(kt + 1); }

#pragma unroll
        for (int kk = 0; kk < BK; kk++) {
            unsigned long long a2[TM / 2];
            const unsigned long long* ap =
                reinterpret_cast<const unsigned long long*>(&As[kk][tm0]);
#pragma unroll
            for (int i = 0; i < TM / 2; i++) a2[i] = ap[i];

            float bf[TN];
#pragma unroll
            for (int n = 0; n < TN; n += 4) {
                float4 b4 = *reinterpret_cast<const float4*>(&Bs[kk][tn0 + n]);
                bf[n] = b4.x; bf[n + 1] = b4.y; bf[n + 2] = b4.z; bf[n + 3] = b4.w;
            }
#pragma unroll
            for (int n = 0; n < TN; n++) {
                unsigned long long bd = dup_f32(bf[n]);
#pragma unroll
                for (int i = 0; i < TM / 2; i++)
                    acc[i][n] = fma_f32x2(a2[i], bd, acc[i][n]);
            }
        }
        __syncthreads();
    }

    // epilogue
    float bv[TN];
    if constexpr (EPI == 1) {
#pragma unroll
        for (int n = 0; n < TN; n++) bv[n] = bias[nBlk + tn0 + n];
    }
#pragma unroll
    for (int i = 0; i < TM / 2; i++) {
        float r0[TN], r1[TN];
#pragma unroll
        for (int n = 0; n < TN; n++) {
            float2 u = unpack_f32x2(acc[i][n]);
            r0[n] = u.x;
            r1[n] = u.y;
        }
#pragma unroll
        for (int n = 0; n < TN; n++) {
            if constexpr (EPI == 1) {
                r0[n] += bv[n];
                r1[n] += bv[n];
            } else if constexpr (EPI == 2) {
                r0[n] = fminf(fmaxf(1.f / (1.f + __expf(-r0[n])), EPS_P), 1.f - EPS_P);
                r1[n] = fminf(fmaxf(1.f / (1.f + __expf(-r1[n])), EPS_P), 1.f - EPS_P);
            }
        }
        size_t row0 = (size_t)(mBlk + tm0 + 2 * i) * ldc + nBlk + tn0;
#pragma unroll
        for (int n = 0; n < TN; n += 4) {
            *reinterpret_cast<float4*>(C + row0 + n) =
                make_float4(r0[n], r0[n + 1], r0[n + 2], r0[n + 3]);
            *reinterpret_cast<float4*>(C + row0 + ldc + n) =
                make_float4(r1[n], r1[n + 1], r1[n + 2], r1[n + 3]);
        }
    }
}

// ---------------- transpose: out(C x R) = in(R x C)^T ----------------
__global__ void transpose_kernel(const float* __restrict__ in, float* __restrict__ out,
                                 int R, int C) {
    __shared__ float tile[32][33];
    int c0 = blockIdx.x * 32;
    int r0 = blockIdx.y * 32;
    int x = threadIdx.x, y0 = threadIdx.y;
#pragma unroll
    for (int yy = y0; yy < 32; yy += 8) {
        int r = r0 + yy, c = c0 + x;
        if (r < R && c < C) tile[yy][x] = in[(size_t)r * C + c];
    }
    __syncthreads();
#pragma unroll
    for (int yy = y0; yy < 32; yy += 8) {
        int c = c0 + yy, r = r0 + x;
        if (r < R && c < C) out[(size_t)c * R + r] = tile[x][yy];
    }
}

// ---------------- monotonic attention scan (in place over P) ----------------
// phi[i,j] = (1 - p[i,j-1]) * phi[i,j-1] + p[i-1,j] * phi[i-1,j]; phi[0] = onehot(0).
// One block per (batch, head). 128 threads x 8 elements. Row recurrence solved by
// per-thread affine compose + warp shfl scan + 4-warp smem prefix (parity buffered).
__global__ void __launch_bounds__(128) monotonic_scan_kernel(float* __restrict__ P) {
    float* p = P + ((size_t)blockIdx.x << 20);
    const int tid = threadIdx.x;
    const int lane = tid & 31;
    const int wid = tid >> 5;
    const int j0 = tid << 3;
    __shared__ float aggA[2][4], aggB[2][4];

    float pPrev[8], phiPrev[8], cur[8];

    {
        float4 t0 = *reinterpret_cast<const float4*>(p + j0);
        float4 t1 = *reinterpret_cast<const float4*>(p + j0 + 4);
        pPrev[0] = t0.x; pPrev[1] = t0.y; pPrev[2] = t0.z; pPrev[3] = t0.w;
        pPrev[4] = t1.x; pPrev[5] = t1.y; pPrev[6] = t1.z; pPrev[7] = t1.w;
    }
#pragma unroll
    for (int x = 0; x < 8; x++) phiPrev[x] = 0.f;
    if (tid == 0) phiPrev[0] = 1.f;
    // write phi row 0 (p row 0 already consumed into registers)
    *reinterpret_cast<float4*>(p + j0) =
        make_float4(phiPrev[0], phiPrev[1], phiPrev[2], phiPrev[3]);
    *reinterpret_cast<float4*>(p + j0 + 4) =
        make_float4(phiPrev[4], phiPrev[5], phiPrev[6], phiPrev[7]);

    float curLeft;
    {
        const float* r = p + 1024;
        float4 c0 = *reinterpret_cast<const float4*>(r + j0);
        float4 c1 = *reinterpret_cast<const float4*>(r + j0 + 4);
        cur[0] = c0.x; cur[1] = c0.y; cur[2] = c0.z; cur[3] = c0.w;
        cur[4] = c1.x; cur[5] = c1.y; cur[6] = c1.z; cur[7] = c1.w;
        curLeft = (tid == 0) ? 0.f : r[j0 - 1];
    }

    for (int i = 1; i < 1024; i++) {
        // prefetch next row (hides DRAM latency behind this row's scan)
        float nxt[8];
        float nxtLeft = 0.f;
        if (i + 1 < 1024) {
            const float* r = p + (size_t)(i + 1) * 1024;
            float4 c0 = *reinterpret_cast<const float4*>(r + j0);
            float4 c1 = *reinterpret_cast<const float4*>(r + j0 + 4);
            nxt[0] = c0.x; nxt[1] = c0.y; nxt[2] = c0.z; nxt[3] = c0.w;
            nxt[4] = c1.x; nxt[5] = c1.y; nxt[6] = c1.z; nxt[7] = c1.w;
            nxtLeft = (tid == 0) ? 0.f : r[j0 - 1];
        }

        float A[8], a[8];
        A[0] = (tid == 0) ? 0.f : (1.f - curLeft);
#pragma unroll
        for (int x = 1; x < 8; x++) A[x] = 1.f - cur[x - 1];
#pragma unroll
        for (int x = 0; x < 8; x++) a[x] = phiPrev[x] * pPrev[x];

        // per-thread affine compose over 8 elements
        float Ac = A[0], bc = a[0];
#pragma unroll
        for (int x = 1; x < 8; x++) {
            bc = fmaf(bc, A[x], a[x]);
            Ac *= A[x];
        }

        // warp inclusive scan of (A,b)
        float sA = Ac, sB = bc;
#pragma unroll
        for (int d = 1; d < 32; d <<= 1) {
            float oA = __shfl_up_sync(0xffffffffu, sA, d);
            float oB = __shfl_up_sync(0xffffffffu, sB, d);
            if (lane >= d) {
                sB = fmaf(oB, sA, sB);
                sA = oA * sA;
            }
        }

        const int par = i & 1;
        if (lane == 31) {
            aggA[par][wid] = sA;
            aggB[par][wid] = sB;
        }
        __syncthreads();

        // prefix over preceding warps (y before this warp's first element)
        float yw = 0.f;
#pragma unroll
        for (int w = 0; w < 3; w++)
            if (w < wid) yw = fmaf(yw, aggA[par][w], aggB[par][w]);

        // exclusive within warp
        float eA = __shfl_up_sync(0xffffffffu, sA, 1);
        float eB = __shfl_up_sync(0xffffffffu, sB, 1);
        if (lane == 0) { eA = 1.f; eB = 0.f; }
        float y = fmaf(yw, eA, eB);  // phi value just before this thread's chunk

        // serial fixup -> phi row i values
#pragma unroll
        for (int x = 0; x < 8; x++) {
            y = fmaf(A[x], y, a[x]);
            phiPrev[x] = y;
        }

        float* orow = p + (size_t)i * 1024 + j0;
        *reinterpret_cast<float4*>(orow) =
            make_float4(phiPrev[0], phiPrev[1], phiPrev[2], phiPrev[3]);
        *reinterpret_cast<float4*>(orow + 4) =
            make_float4(phiPrev[4], phiPrev[5], phiPrev[6], phiPrev[7]);

#pragma unroll
        for (int x = 0; x < 8; x++) pPrev[x] = cur[x];
        if (i + 1 < 1024) {
#pragma unroll
            for (int x = 0; x < 8; x++) cur[x] = nxt[x];
            curLeft = nxtLeft;
        }
    }
}

// ---------------- launch ----------------
extern "C" void kernel_launch(void* const* d_in, const int* in_sizes, int n_in,
                              void* d_out, int out_size) {
    (void)in_sizes; (void)n_in; (void)out_size;
    const float* query = (const float*)d_in[0];
    const float* key   = (const float*)d_in[1];
    const float* value = (const float*)d_in[2];
    const float* Win   = (const float*)d_in[3];
    const float* bin   = (const float*)d_in[4];
    const float* Wout  = (const float*)d_in[5];
    const float* bout  = (const float*)d_in[6];
    float* out = (float*)d_out;

    float *WinT, *WoutT, *Q, *Kb, *Vb, *KT, *P, *XO;
    cudaGetSymbolAddress((void**)&WinT, g_WinT);
    cudaGetSymbolAddress((void**)&WoutT, g_WoutT);
    cudaGetSymbolAddress((void**)&Q, g_Q);
    cudaGetSymbolAddress((void**)&Kb, g_K);
    cudaGetSymbolAddress((void**)&Vb, g_V);
    cudaGetSymbolAddress((void**)&KT, g_KT);
    cudaGetSymbolAddress((void**)&P, g_P);
    cudaGetSymbolAddress((void**)&XO, g_XO);

    dim3 tb(32, 8);
    // weight transposes (W is (out,in); we need (in,out) for NN GEMM)
    transpose_kernel<<<dim3(1024 / 32, 1536 / 32), tb>>>(Win, WinT, 1536, 1024);
    transpose_kernel<<<dim3(1024 / 32, 1024 / 32), tb>>>(Wout, WoutT, 1024, 1024);

    // Q projection: (2048x1024) = query (2048x1024) @ WinT[:, 0:1024]
    gemm_nn<128, 128, 16, 8, 8, 0, 1><<<dim3(8, 16, 1), 256>>>(
        query, WinT, Q, bin, 2048, 1024, 1024, 1024, 1536, 1024);
    // K projection: (2048x256) = key @ WinT[:, 1024:1280]
    gemm_nn<64, 128, 16, 8, 8, 0, 1><<<dim3(2, 32, 1), 128>>>(
        key, WinT + 1024, Kb, bin + 1024, 2048, 256, 1024, 1024, 1536, 256);
    // V projection: (2048x256) = value @ WinT[:, 1280:1536]
    gemm_nn<64, 128, 16, 8, 8, 0, 1><<<dim3(2, 32, 1), 128>>>(
        value, WinT + 1280, Vb, bin + 1280, 2048, 256, 1024, 1024, 1536, 256);

    // K transpose to (embed x token) for NN score GEMM
    transpose_kernel<<<dim3(256 / 32, 2048 / 32), tb>>>(Kb, KT, 2048, 256);

    // scores per head: P = clamp(sigmoid(Qh @ Kh^T), eps, 1-eps); 32 heads in grid.z
    gemm_nn<128, 128, 16, 8, 8, 1, 2><<<dim3(8, 8, 32), 256>>>(
        Q, KT, P, nullptr, 1024, 1024, 64, 1024, 2048, 1024);

    // monotonic attention recurrence (in place: P -> phi)
    monotonic_scan_kernel<<<32, 128>>>(P);

    // O = phi @ V per head, scattered into XO (token-major, per-head columns)
    gemm_nn<128, 64, 16, 8, 8, 2, 0><<<dim3(1, 8, 32), 128>>>(
        P, Vb, XO, nullptr, 1024, 64, 1024, 1024, 256, 1024);

    // output projection
    gemm_nn<128, 128, 16, 8, 8, 0, 1><<<dim3(8, 16, 1), 256>>>(
        XO, WoutT, out, bout, 2048, 1024, 1024, 1024, 1024, 1024);
}

// round 9
// speedup vs baseline: 1.0167x; 1.0042x over previous
#include <cuda_runtime.h>
#include <cstdint>

#define EPS_P 0.001f

// ---------------- scratch (device globals: no allocation, graph-safe) ----------------
__device__ float g_WinT[1024 * 1536];   // in_proj_weight^T  (K=1024 x N=1536)
__device__ float g_WoutT[1024 * 1024];  // out_proj_weight^T (1024 x 1024)
__device__ float g_Q[2048 * 1024];      // projected queries
__device__ float g_K[2048 * 256];       // projected keys
__device__ float g_V[2048 * 256];       // projected values
__device__ float g_KT[256 * 2048];      // keys transposed (embed x token)
__device__ float g_P[32 * 1024 * 1024]; // sigmoid probs -> phi (in place)
__device__ float g_XO[2048 * 1024];     // attention output (token-major, per-head cols)

// ---------------- f32x2 packed-FMA helpers (FFMA2 only reachable via PTX) ----------------
__device__ __forceinline__ unsigned long long fma_f32x2(unsigned long long a,
                                                        unsigned long long b,
                                                        unsigned long long c) {
    unsigned long long d;
    asm("fma.rn.f32x2 %0, %1, %2, %3;" : "=l"(d) : "l"(a), "l"(b), "l"(c));
    return d;
}
__device__ __forceinline__ unsigned long long dup_f32(float x) {
    unsigned long long d;
    asm("mov.b64 %0, {%1, %1};" : "=l"(d) : "f"(x));
    return d;
}
__device__ __forceinline__ float2 unpack_f32x2(unsigned long long v) {
    float2 r;
    asm("mov.b64 {%0, %1}, %2;" : "=f"(r.x), "=f"(r.y) : "l"(v));
    return r;
}

// ---------------- generic NN SGEMM: C(MxN) = A(MxK) * B(KxN) [+bias / sigmoid-clip] ----
// MODE 0: plain (blockIdx.z unused)
// MODE 1: scores   — per-head offsets (A=Q head slice, B=K^T head slice, C=P slice)
// MODE 2: phi @ V  — per-head offsets (A=phi slice, B=V head slice, C=XO head cols)
// EPI  0: none, 1: +bias[n], 2: clamp(sigmoid(x), eps, 1-eps)
template <int BM, int BN, int BK, int TM, int TN, int MODE, int EPI>
__global__ void __launch_bounds__((BM / TM) * (BN / TN))
gemm_nn(const float* __restrict__ A, const float* __restrict__ B, float* __restrict__ C,
        const float* __restrict__ bias, int M, int N, int K,
        int lda, int ldb, int ldc) {
    constexpr int NT = (BM / TM) * (BN / TN);
    constexpr int AVEC = BM * BK / 4;
    constexpr int BVEC = BK * BN / 4;
    constexpr int APT = AVEC / NT;
    constexpr int BPT = BVEC / NT;
    static_assert(AVEC % NT == 0 && BVEC % NT == 0, "tile/thread mismatch");
    static_assert((TM % 2) == 0, "TM even for f32x2");

    __shared__ float As[BK][BM];
    __shared__ float Bs[BK][BN];

    const int z = blockIdx.z;
    if constexpr (MODE == 1) {
        A += (z >> 4) * (1024 * 1024) + (z & 15) * 64;   // Q: batch + q-head col
        B += (z & 3) * (64 * 2048) + (z >> 4) * 1024;    // K^T: kv-head rows + batch cols
        C += z << 20;                                    // P slice
    } else if constexpr (MODE == 2) {
        A += z << 20;                                    // phi slice
        B += (z >> 4) * (1024 * 256) + (z & 3) * 64;     // V: batch rows + kv-head cols
        C += (z >> 4) * (1024 * 1024) + (z & 15) * 64;   // XO: batch + q-head cols
    }

    const int tid = threadIdx.x;
    const int mBlk = blockIdx.y * BM;
    const int nBlk = blockIdx.x * BN;
    const int tn0 = (tid % (BN / TN)) * TN;
    const int tm0 = (tid / (BN / TN)) * TM;
    const int nTiles = K / BK;

    unsigned long long acc[TM / 2][TN];
#pragma unroll
    for (int i = 0; i < TM / 2; i++)
#pragma unroll
        for (int n = 0; n < TN; n++) acc[i][n] = 0ull;

    float4 aReg[APT], bReg[BPT];

    auto loadA = [&](int kt) {
#pragma unroll
        for (int q = 0; q < APT; q++) {
            int v = tid + q * NT;
            int m = v / (BK / 4);
            int kq = v % (BK / 4);
            aReg[q] = *reinterpret_cast<const float4*>(
                A + (size_t)(mBlk + m) * lda + kt * BK + kq * 4);
        }
    };
    auto loadB = [&](int kt) {
#pragma unroll
        for (int q = 0; q < BPT; q++) {
            int v = tid + q * NT;
            int k = v / (BN / 4);
            int nq = v % (BN / 4);
            bReg[q] = *reinterpret_cast<const float4*>(
                B + (size_t)(kt * BK + k) * ldb + nBlk + nq * 4);
        }
    };

    loadA(0);
    loadB(0);

    for (int kt = 0; kt < nTiles; kt++) {
#pragma unroll
        for (int q = 0; q < APT; q++) {
            int v = tid + q * NT;
            int m = v / (BK / 4);
            int kq = v % (BK / 4);
            As[kq * 4 + 0][m] = aReg[q].x;
            As[kq * 4 + 1][m] = aReg[q].y;
            As[kq * 4 + 2][m] = aReg[q].z;
            As[kq * 4 + 3][m] = aReg[q].w;
        }
#pragma unroll
        for (int q = 0; q < BPT; q++) {
            int v = tid + q * NT;
            int k = v / (BN / 4);
            int nq = v % (BN / 4);
            *reinterpret_cast<float4*>(&Bs[k][nq * 4]) = bReg[q];
        }
        __syncthreads();

        if (kt + 1 < nTiles) { loadA(kt + 1); loadB(kt + 1); }

#pragma unroll
        for (int kk = 0; kk < BK; kk++) {
            unsigned long long a2[TM / 2];
            const unsigned long long* ap =
                reinterpret_cast<const unsigned long long*>(&As[kk][tm0]);
#pragma unroll
            for (int i = 0; i < TM / 2; i++) a2[i] = ap[i];

            float bf[TN];
#pragma unroll
            for (int n = 0; n < TN; n += 4) {
                float4 b4 = *reinterpret_cast<const float4*>(&Bs[kk][tn0 + n]);
                bf[n] = b4.x; bf[n + 1] = b4.y; bf[n + 2] = b4.z; bf[n + 3] = b4.w;
            }
#pragma unroll
            for (int n = 0; n < TN; n++) {
                unsigned long long bd = dup_f32(bf[n]);
#pragma unroll
                for (int i = 0; i < TM / 2; i++)
                    acc[i][n] = fma_f32x2(a2[i], bd, acc[i][n]);
            }
        }
        __syncthreads();
    }

    // epilogue
    float bv[TN];
    if constexpr (EPI == 1) {
#pragma unroll
        for (int n = 0; n < TN; n++) bv[n] = bias[nBlk + tn0 + n];
    }
#pragma unroll
    for (int i = 0; i < TM / 2; i++) {
        float r0[TN], r1[TN];
#pragma unroll
        for (int n = 0; n < TN; n++) {
            float2 u = unpack_f32x2(acc[i][n]);
            r0[n] = u.x;
            r1[n] = u.y;
        }
#pragma unroll
        for (int n = 0; n < TN; n++) {
            if constexpr (EPI == 1) {
                r0[n] += bv[n];
                r1[n] += bv[n];
            } else if constexpr (EPI == 2) {
                r0[n] = fminf(fmaxf(1.f / (1.f + __expf(-r0[n])), EPS_P), 1.f - EPS_P);
                r1[n] = fminf(fmaxf(1.f / (1.f + __expf(-r1[n])), EPS_P), 1.f - EPS_P);
            }
        }
        size_t row0 = (size_t)(mBlk + tm0 + 2 * i) * ldc + nBlk + tn0;
#pragma unroll
        for (int n = 0; n < TN; n += 4) {
            *reinterpret_cast<float4*>(C + row0 + n) =
                make_float4(r0[n], r0[n + 1], r0[n + 2], r0[n + 3]);
            *reinterpret_cast<float4*>(C + row0 + ldc + n) =
                make_float4(r1[n], r1[n + 1], r1[n + 2], r1[n + 3]);
        }
    }
}

// ---------------- transpose: out(C x R) = in(R x C)^T ----------------
__global__ void transpose_kernel(const float* __restrict__ in, float* __restrict__ out,
                                 int R, int C) {
    __shared__ float tile[32][33];
    int c0 = blockIdx.x * 32;
    int r0 = blockIdx.y * 32;
    int x = threadIdx.x, y0 = threadIdx.y;
#pragma unroll
    for (int yy = y0; yy < 32; yy += 8) {
        int r = r0 + yy, c = c0 + x;
        if (r < R && c < C) tile[yy][x] = in[(size_t)r * C + c];
    }
    __syncthreads();
#pragma unroll
    for (int yy = y0; yy < 32; yy += 8) {
        int c = c0 + yy, r = r0 + x;
        if (r < R && c < C) out[(size_t)c * R + r] = tile[x][yy];
    }
}

// ---------------- monotonic attention scan (in place over P) ----------------
// phi[i,j] = (1 - p[i,j-1]) * phi[i,j-1] + p[i-1,j] * phi[i-1,j]; phi[0] = onehot(0).
// One block per (batch, head). 128 threads x 8 elements. Row recurrence solved by
// per-thread affine compose + warp shfl scan + 4-warp smem prefix (parity buffered).
__global__ void __launch_bounds__(128) monotonic_scan_kernel(float* __restrict__ P) {
    float* p = P + ((size_t)blockIdx.x << 20);
    const int tid = threadIdx.x;
    const int lane = tid & 31;
    const int wid = tid >> 5;
    const int j0 = tid << 3;
    __shared__ float aggA[2][4], aggB[2][4];

    float pPrev[8], phiPrev[8], cur[8];

    {
        float4 t0 = *reinterpret_cast<const float4*>(p + j0);
        float4 t1 = *reinterpret_cast<const float4*>(p + j0 + 4);
        pPrev[0] = t0.x; pPrev[1] = t0.y; pPrev[2] = t0.z; pPrev[3] = t0.w;
        pPrev[4] = t1.x; pPrev[5] = t1.y; pPrev[6] = t1.z; pPrev[7] = t1.w;
    }
#pragma unroll
    for (int x = 0; x < 8; x++) phiPrev[x] = 0.f;
    if (tid == 0) phiPrev[0] = 1.f;
    // write phi row 0 (p row 0 already consumed into registers)
    *reinterpret_cast<float4*>(p + j0) =
        make_float4(phiPrev[0], phiPrev[1], phiPrev[2], phiPrev[3]);
    *reinterpret_cast<float4*>(p + j0 + 4) =
        make_float4(phiPrev[4], phiPrev[5], phiPrev[6], phiPrev[7]);

    float curLeft;
    {
        const float* r = p + 1024;
        float4 c0 = *reinterpret_cast<const float4*>(r + j0);
        float4 c1 = *reinterpret_cast<const float4*>(r + j0 + 4);
        cur[0] = c0.x; cur[1] = c0.y; cur[2] = c0.z; cur[3] = c0.w;
        cur[4] = c1.x; cur[5] = c1.y; cur[6] = c1.z; cur[7] = c1.w;
        curLeft = (tid == 0) ? 0.f : r[j0 - 1];
    }

    for (int i = 1; i < 1024; i++) {
        // prefetch next row (hides DRAM latency behind this row's scan)
        float nxt[8];
        float nxtLeft = 0.f;
        if (i + 1 < 1024) {
            const float* r = p + (size_t)(i + 1) * 1024;
            float4 c0 = *reinterpret_cast<const float4*>(r + j0);
            float4 c1 = *reinterpret_cast<const float4*>(r + j0 + 4);
            nxt[0] = c0.x; nxt[1] = c0.y; nxt[2] = c0.z; nxt[3] = c0.w;
            nxt[4] = c1.x; nxt[5] = c1.y; nxt[6] = c1.z; nxt[7] = c1.w;
            nxtLeft = (tid == 0) ? 0.f : r[j0 - 1];
        }

        float A[8], a[8];
        A[0] = (tid == 0) ? 0.f : (1.f - curLeft);
#pragma unroll
        for (int x = 1; x < 8; x++) A[x] = 1.f - cur[x - 1];
#pragma unroll
        for (int x = 0; x < 8; x++) a[x] = phiPrev[x] * pPrev[x];

        // per-thread affine compose over 8 elements
        float Ac = A[0], bc = a[0];
#pragma unroll
        for (int x = 1; x < 8; x++) {
            bc = fmaf(bc, A[x], a[x]);
            Ac *= A[x];
        }

        // warp inclusive scan of (A,b)
        float sA = Ac, sB = bc;
#pragma unroll
        for (int d = 1; d < 32; d <<= 1) {
            float oA = __shfl_up_sync(0xffffffffu, sA, d);
            float oB = __shfl_up_sync(0xffffffffu, sB, d);
            if (lane >= d) {
                sB = fmaf(oB, sA, sB);
                sA = oA * sA;
            }
        }

        const int par = i & 1;
        if (lane == 31) {
            aggA[par][wid] = sA;
            aggB[par][wid] = sB;
        }
        __syncthreads();

        // prefix over preceding warps (y before this warp's first element)
        float yw = 0.f;
#pragma unroll
        for (int w = 0; w < 3; w++)
            if (w < wid) yw = fmaf(yw, aggA[par][w], aggB[par][w]);

        // exclusive within warp
        float eA = __shfl_up_sync(0xffffffffu, sA, 1);
        float eB = __shfl_up_sync(0xffffffffu, sB, 1);
        if (lane == 0) { eA = 1.f; eB = 0.f; }
        float y = fmaf(yw, eA, eB);  // phi value just before this thread's chunk

        // serial fixup -> phi row i values
#pragma unroll
        for (int x = 0; x < 8; x++) {
            y = fmaf(A[x], y, a[x]);
            phiPrev[x] = y;
        }

        float* orow = p + (size_t)i * 1024 + j0;
        *reinterpret_cast<float4*>(orow) =
            make_float4(phiPrev[0], phiPrev[1], phiPrev[2], phiPrev[3]);
        *reinterpret_cast<float4*>(orow + 4) =
            make_float4(phiPrev[4], phiPrev[5], phiPrev[6], phiPrev[7]);

#pragma unroll
        for (int x = 0; x < 8; x++) pPrev[x] = cur[x];
        if (i + 1 < 1024) {
#pragma unroll
            for (int x = 0; x < 8; x++) cur[x] = nxt[x];
            curLeft = nxtLeft;
        }
    }
}

// ---------------- launch ----------------
extern "C" void kernel_launch(void* const* d_in, const int* in_sizes, int n_in,
                              void* d_out, int out_size) {
    (void)in_sizes; (void)n_in; (void)out_size;
    const float* query = (const float*)d_in[0];
    const float* key   = (const float*)d_in[1];
    const float* value = (const float*)d_in[2];
    const float* Win   = (const float*)d_in[3];
    const float* bin   = (const float*)d_in[4];
    const float* Wout  = (const float*)d_in[5];
    const float* bout  = (const float*)d_in[6];
    float* out = (float*)d_out;

    float *WinT, *WoutT, *Q, *Kb, *Vb, *KT, *P, *XO;
    cudaGetSymbolAddress((void**)&WinT, g_WinT);
    cudaGetSymbolAddress((void**)&WoutT, g_WoutT);
    cudaGetSymbolAddress((void**)&Q, g_Q);
    cudaGetSymbolAddress((void**)&Kb, g_K);
    cudaGetSymbolAddress((void**)&Vb, g_V);
    cudaGetSymbolAddress((void**)&KT, g_KT);
    cudaGetSymbolAddress((void**)&P, g_P);
    cudaGetSymbolAddress((void**)&XO, g_XO);

    dim3 tb(32, 8);
    // weight transposes (W is (out,in); we need (in,out) for NN GEMM)
    transpose_kernel<<<dim3(1024 / 32, 1536 / 32), tb>>>(Win, WinT, 1536, 1024);
    transpose_kernel<<<dim3(1024 / 32, 1024 / 32), tb>>>(Wout, WoutT, 1024, 1024);

    // Q projection: (2048x1024) = query (2048x1024) @ WinT[:, 0:1024]
    gemm_nn<128, 128, 16, 8, 8, 0, 1><<<dim3(8, 16, 1), 256>>>(
        query, WinT, Q, bin, 2048, 1024, 1024, 1024, 1536, 1024);
    // K projection: (2048x256) = key @ WinT[:, 1024:1280]
    gemm_nn<64, 128, 16, 8, 8, 0, 1><<<dim3(2, 32, 1), 128>>>(
        key, WinT + 1024, Kb, bin + 1024, 2048, 256, 1024, 1024, 1536, 256);
    // V projection: (2048x256) = value @ WinT[:, 1280:1536]
    gemm_nn<64, 128, 16, 8, 8, 0, 1><<<dim3(2, 32, 1), 128>>>(
        value, WinT + 1280, Vb, bin + 1280, 2048, 256, 1024, 1024, 1536, 256);

    // K transpose to (embed x token) for NN score GEMM
    transpose_kernel<<<dim3(256 / 32, 2048 / 32), tb>>>(Kb, KT, 2048, 256);

    // scores per head: P = clamp(sigmoid(Qh @ Kh^T), eps, 1-eps); 32 heads in grid.z
    gemm_nn<128, 128, 16, 8, 8, 1, 2><<<dim3(8, 8, 32), 256>>>(
        Q, KT, P, nullptr, 1024, 1024, 64, 1024, 2048, 1024);

    // monotonic attention recurrence (in place: P -> phi)
    monotonic_scan_kernel<<<32, 128>>>(P);

    // O = phi @ V per head, scattered into XO (token-major, per-head columns)
    gemm_nn<128, 64, 16, 8, 8, 2, 0><<<dim3(1, 8, 32), 128>>>(
        P, Vb, XO, nullptr, 1024, 64, 1024, 1024, 256, 1024);

    // output projection
    gemm_nn<128, 128, 16, 8, 8, 0, 1><<<dim3(8, 16, 1), 256>>>(
        XO, WoutT, out, bout, 2048, 1024, 1024, 1024, 1024, 1024);
}